// round 6
// baseline (speedup 1.0000x reference)
#include <cuda_runtime.h>
#include <cuda_bf16.h>

// AbsDiff cost volume:
//   out[n, d, y, x] = |image1[n,0,y,x] - image2[n,0,y,x-d]|  if x-d >= 0 else 0
// in [2,1,384,1248] fp32, out [2,128,384,1248] fp32. HBM-write-bound (~491MB,
// floor 61.4us @ 8TB/s; we're at ~90% effective). R6: D_CHUNK 8->16 in two
// register-window phases (peak live regs unchanged -> occ 8 kept). Halves
// input L2 re-read traffic and block count; stores unchanged (STG.128 .cs).

#define W_DIM    1248
#define H_DIM    384
#define N_DIM    2
#define D_DIM    128
#define W4       (W_DIM / 4)          // 312
#define THREADS  256
#define D_CHUNK  16                   // d0 = 16*blockIdx.y
#define XY_BLKS  ((N_DIM * H_DIM * W4) / THREADS)   // 936, exact

__device__ __forceinline__ void stcs4(float4* p, float4 v) {
    asm volatile("st.global.cs.v4.f32 [%0], {%1,%2,%3,%4};"
                 :: "l"(p), "f"(v.x), "f"(v.y), "f"(v.z), "f"(v.w) : "memory");
}

__global__ __launch_bounds__(THREADS, 8)
void absdiff_costvol_kernel(const float* __restrict__ left,
                            const float* __restrict__ right,
                            float* __restrict__ out)
{
    // Flat id over (n, y, x4): x4 fastest so warps are x-contiguous.
    const int gid = blockIdx.x * THREADS + threadIdx.x;   // < 239616
    const int x4  = gid % W4;
    const int ny  = gid / W4;                             // n*H + y, < 768
    const int d0  = blockIdx.y * D_CHUNK;                 // multiple of 16

    const int x0 = 4 * x4;

    const float4 L = reinterpret_cast<const float4*>(
                         left + (size_t)ny * W_DIM)[x4];

    const float4* rrow4 = reinterpret_cast<const float4*>(
                              right + (size_t)ny * W_DIM);

    // Phase-A window: floats [x0-d0-8, x0-d0+3]  (float4 blocks b, b+1, b+2).
    // Negative block indices are clamped to 0 — those floats feed only
    // mask-zeroed outputs (x < d there).
    const int b = x4 - d0 / 4 - 2;      // <= 309; may be negative
    {
        const int b0 = b     < 0 ? 0 : b;
        const int b1 = b + 1 < 0 ? 0 : b + 1;
        const int b2 = b + 2 < 0 ? 0 : b + 2;

        float w[12];
        const float4 X = rrow4[b0];
        const float4 Y = rrow4[b1];
        const float4 Z = rrow4[b2];
        w[0]=X.x; w[1]=X.y; w[2]=X.z;  w[3]=X.w;
        w[4]=Y.x; w[5]=Y.y; w[6]=Y.z;  w[7]=Y.w;
        w[8]=Z.x; w[9]=Z.y; w[10]=Z.z; w[11]=Z.w;

        const int n = ny / H_DIM;
        const int y = ny % H_DIM;
        float* ob = out + ((size_t)(n * D_DIM + d0) * H_DIM + y) * W_DIM + x0;

        #pragma unroll
        for (int k = 0; k < 8; ++k) {
            const int d  = d0 + k;
            const int j0 = 8 - k;            // compile-time offset
            float4 v;
            v.x = (x0 + 0 >= d) ? fabsf(L.x - w[j0 + 0]) : 0.f;
            v.y = (x0 + 1 >= d) ? fabsf(L.y - w[j0 + 1]) : 0.f;
            v.z = (x0 + 2 >= d) ? fabsf(L.z - w[j0 + 2]) : 0.f;
            v.w = (x0 + 3 >= d) ? fabsf(L.w - w[j0 + 3]) : 0.f;
            stcs4((float4*)(ob + (size_t)k * (H_DIM * W_DIM)), v);
        }

        // Phase-B window: floats [x0-d0-16, x0-d0-5]
        // (blocks b-2, b-1, b; block b floats == phase-A w[0..3]).
        const int bm2 = b - 2 < 0 ? 0 : b - 2;
        const int bm1 = b - 1 < 0 ? 0 : b - 1;

        float u[12];
        const float4 P = rrow4[bm2];
        const float4 Q = rrow4[bm1];
        u[0]=P.x; u[1]=P.y; u[2]=P.z;  u[3]=P.w;
        u[4]=Q.x; u[5]=Q.y; u[6]=Q.z;  u[7]=Q.w;
        u[8]=w[0]; u[9]=w[1]; u[10]=w[2]; u[11]=w[3];

        #pragma unroll
        for (int k = 8; k < 16; ++k) {
            const int d  = d0 + k;
            const int j0 = 16 - k;           // 8..1, compile-time
            float4 v;
            v.x = (x0 + 0 >= d) ? fabsf(L.x - u[j0 + 0]) : 0.f;
            v.y = (x0 + 1 >= d) ? fabsf(L.y - u[j0 + 1]) : 0.f;
            v.z = (x0 + 2 >= d) ? fabsf(L.z - u[j0 + 2]) : 0.f;
            v.w = (x0 + 3 >= d) ? fabsf(L.w - u[j0 + 3]) : 0.f;
            stcs4((float4*)(ob + (size_t)k * (H_DIM * W_DIM)), v);
        }
    }
}

extern "C" void kernel_launch(void* const* d_in, const int* in_sizes, int n_in,
                              void* d_out, int out_size)
{
    const float* image1 = (const float*)d_in[0];  // left
    const float* image2 = (const float*)d_in[1];  // right (shifted source)
    float* out = (float*)d_out;

    (void)in_sizes; (void)n_in; (void)out_size;

    dim3 grid(XY_BLKS, D_DIM / D_CHUNK);   // 936 x 8 = 7488 blocks
    dim3 block(THREADS);
    absdiff_costvol_kernel<<<grid, block>>>(image1, image2, out);
}

// round 7
// speedup vs baseline: 1.0312x; 1.0312x over previous
#include <cuda_runtime.h>
#include <cuda_bf16.h>

// AbsDiff cost volume:
//   out[n, d, y, x] = |image1[n,0,y,x] - image2[n,0,y,x-d]|  if x-d >= 0 else 0
// in [2,1,384,1248] fp32, out [2,128,384,1248] fp32. HBM-write-bound (~491MB).
// R7: R5 structure (no smem/sync, 12-float register window, 8 STG.128 .cs per
// thread) but 64-thread CTAs at occ 32 (still 64 warps/SM). 4x more, 4x
// shorter CTAs shrink the partial-wave tail from ~2.8% to ~0.7% and smooth
// store-queue pressure across wave boundaries.

#define W_DIM    1248
#define H_DIM    384
#define N_DIM    2
#define D_DIM    128
#define W4       (W_DIM / 4)          // 312
#define THREADS  64                   // 2 warps; occ 32 -> 64 warps/SM
#define D_CHUNK  8                    // d0 = 8*blockIdx.y
#define XY_BLKS  ((N_DIM * H_DIM * W4) / THREADS)   // 3744, exact

__device__ __forceinline__ void stcs4(float4* p, float4 v) {
    asm volatile("st.global.cs.v4.f32 [%0], {%1,%2,%3,%4};"
                 :: "l"(p), "f"(v.x), "f"(v.y), "f"(v.z), "f"(v.w) : "memory");
}

__global__ __launch_bounds__(THREADS, 32)
void absdiff_costvol_kernel(const float* __restrict__ left,
                            const float* __restrict__ right,
                            float* __restrict__ out)
{
    // Flat id over (n, y, x4): x4 fastest so warps are x-contiguous.
    const int gid = blockIdx.x * THREADS + threadIdx.x;   // < 239616
    const int x4  = gid % W4;
    const int ny  = gid / W4;                             // n*H + y, < 768
    const int d0  = blockIdx.y * D_CHUNK;

    const int x0 = 4 * x4;

    // Left float4 (always in-bounds, aligned).
    const float4 L = reinterpret_cast<const float4*>(
                         left + (size_t)ny * W_DIM)[x4];

    // Window: floats [x0-d0-8, x0-d0+3] of the right row, float4-aligned.
    // Negative base float4s clamp to 0 — those slots feed only mask-zeroed
    // outputs (x < d there).
    const float4* rrow4 = reinterpret_cast<const float4*>(
                              right + (size_t)ny * W_DIM);
    const int b  = x4 - d0 / 4 - 2;      // may be negative, <= 309
    const int b0 = b     < 0 ? 0 : b;
    const int b1 = b + 1 < 0 ? 0 : b + 1;
    const int b2 = b + 2 < 0 ? 0 : b + 2;

    float w[12];
    {
        const float4 X = rrow4[b0];
        const float4 Y = rrow4[b1];
        const float4 Z = rrow4[b2];
        w[0]=X.x; w[1]=X.y; w[2]=X.z;  w[3]=X.w;
        w[4]=Y.x; w[5]=Y.y; w[6]=Y.z;  w[7]=Y.w;
        w[8]=Z.x; w[9]=Z.y; w[10]=Z.z; w[11]=Z.w;
    }

    const int n = ny / H_DIM;
    const int y = ny % H_DIM;
    float* ob = out + ((size_t)(n * D_DIM + d0) * H_DIM + y) * W_DIM + x0;

    #pragma unroll
    for (int k = 0; k < D_CHUNK; ++k) {
        const int d  = d0 + k;
        const int j0 = 8 - k;            // compile-time window offset

        float4 v;
        v.x = (x0 + 0 >= d) ? fabsf(L.x - w[j0 + 0]) : 0.f;
        v.y = (x0 + 1 >= d) ? fabsf(L.y - w[j0 + 1]) : 0.f;
        v.z = (x0 + 2 >= d) ? fabsf(L.z - w[j0 + 2]) : 0.f;
        v.w = (x0 + 3 >= d) ? fabsf(L.w - w[j0 + 3]) : 0.f;

        stcs4((float4*)(ob + (size_t)k * (H_DIM * W_DIM)), v);
    }
}

extern "C" void kernel_launch(void* const* d_in, const int* in_sizes, int n_in,
                              void* d_out, int out_size)
{
    const float* image1 = (const float*)d_in[0];  // left
    const float* image2 = (const float*)d_in[1];  // right (shifted source)
    float* out = (float*)d_out;

    (void)in_sizes; (void)n_in; (void)out_size;

    dim3 grid(XY_BLKS, D_DIM / D_CHUNK);   // 3744 x 16 = 59904 blocks
    dim3 block(THREADS);
    absdiff_costvol_kernel<<<grid, block>>>(image1, image2, out);
}